// round 1
// baseline (speedup 1.0000x reference)
#include <cuda_runtime.h>

#define BLK 64      // batches per CTA == threads per CTA
#define NN  64      // number of unknowns (N)
#define NP  65      // N + 1
#define LAM3  1e-4f // V_LAMBDA / DT^6 (DT = 1)
#define RIDGE 1e-4f

// Shared layout (floats):
//  sth : NP*BLK   theta staging (reused as output staging)
//  sgx : NN*BLK   dxy x
//  sgy : NN*BLK   dxy y
//  sL1 : NN*BLK   L[j+1][j]
//  sL2 : NN*BLK   L[j+2][j]
//  sL3 : NN*BLK   L[j+3][j]
//  sinv: NN*BLK   1 / L[j][j]
//  sz  : NN*BLK   forward-solve result / solution
//  sCb : 4*NP     constant DTD band coefficients C(a,m)
#define SMEM_FLOATS (NP*BLK + 7*NN*BLK + 4*NP)

__global__ __launch_bounds__(BLK) void AlpamayoR1_solve_kernel(
    const float* __restrict__ dxy,
    const float* __restrict__ theta,
    const float* __restrict__ v0,
    float* __restrict__ out, int B)
{
    extern __shared__ float sm[];
    float* sth  = sm;
    float* sgx  = sth  + NP*BLK;
    float* sgy  = sgx  + NN*BLK;
    float* sL1  = sgy  + NN*BLK;
    float* sL2  = sL1  + NN*BLK;
    float* sL3  = sL2  + NN*BLK;
    float* sinv = sL3  + NN*BLK;
    float* sz   = sinv + NN*BLK;
    float* sCb  = sz   + NN*BLK;

    const int t  = threadIdx.x;
    const int b0 = blockIdx.x * BLK;

    // ---- constant DTD band: C(a,m) = lam3 * sum_r D3[r,a]*D3[r,a+m] ----
    // D3 row r has coef[t] at column r+t, coef = {-1,3,-3,1}, rows r in [0, NP-4].
    for (int a = t; a < NP; a += BLK) {
        const float coef[4] = {-1.f, 3.f, -3.f, 1.f};
        const int Mrows = NP - 3;  // 62
        #pragma unroll
        for (int m = 0; m < 4; m++) {
            float acc = 0.f;
            int tmin = a - (Mrows - 1); if (tmin < 0) tmin = 0;
            int tmax = 3 - m;           if (tmax > a) tmax = a;
            for (int tt = tmin; tt <= tmax; tt++) acc += coef[tt] * coef[tt + m];
            sCb[m * NP + a] = LAM3 * acc;
        }
    }

    // ---- coalesced load + transpose into shared ----
    for (int idx = t; idx < BLK * NP; idx += BLK) {
        int bl = idx / NP;
        int k  = idx - bl * NP;
        sth[k * BLK + bl] = theta[(size_t)b0 * NP + idx];
    }
    for (int idx = t; idx < BLK * NN * 2; idx += BLK) {
        float v = dxy[(size_t)b0 * NN * 2 + idx];
        int bl = idx / (2 * NN);
        int r  = idx - bl * 2 * NN;
        int i  = r >> 1;
        if (r & 1) sgy[i * BLK + bl] = v;
        else       sgx[i * BLK + bl] = v;
    }
    float v0v = v0[b0 + t];
    __syncthreads();

    // ---- per-thread band assembly + band Cholesky + fused forward solve ----
    // cs/sn streaming with one-step lookahead.
    float th0 = sth[t];
    float c0  = cosf(th0), s0 = sinf(th0);
    float th1 = sth[BLK + t];
    float cA  = cosf(th1), sA = sinf(th1);     // cos/sin of theta[j+1]
    const float e0 = c0 * cA + s0 * sA;        // ATA[0][1] = ATA[1][0]

    #pragma unroll 4
    for (int j = 0; j < NN; ++j) {
        // lookahead: theta[j+2] -> e[j+1] for the super-diagonal
        float cB = 0.f, sB = 0.f, e1 = 0.f;
        if (j <= NN - 2) {
            float th2 = sth[(j + 2) * BLK + t];
            cB = cosf(th2); sB = sinf(th2);
            e1 = cA * cB + sA * sB;
        }

        // rhs[j]
        float gxj = sgx[j * BLK + t];
        float gyj = sgy[j * BLK + t];
        float gx1 = 0.f, gy1 = 0.f;
        if (j <= NN - 2) { gx1 = sgx[(j + 1) * BLK + t]; gy1 = sgy[(j + 1) * BLK + t]; }
        float rhs = 2.f * (cA * (gxj + gx1) + sA * (gyj + gy1));
        // rhs -= (ATA[j+1,0] + DTD[j+1,0]) * v0
        if (j == 0) rhs -= (e0 - 3.f * LAM3) * v0v;
        if (j == 1) rhs -= ( 3.f * LAM3) * v0v;
        if (j == 2) rhs -= (-1.f * LAM3) * v0v;

        // band of lhs, column j (a[m] = lhs[j+m][j])
        float a0 = ((j < NN - 1) ? 2.f : 1.f) + sCb[0 * NP + (j + 1)] + RIDGE;
        float a1 = e1 + sCb[1 * NP + (j + 1)];
        float a2 = sCb[2 * NP + (j + 1)];
        float a3 = sCb[3 * NP + (j + 1)];

        // pivot: d = a0 - sum_m Lb[m][j-m]^2
        float d = a0;
        if (j >= 1) { float x = sL1[(j - 1) * BLK + t]; d -= x * x; }
        if (j >= 2) { float x = sL2[(j - 2) * BLK + t]; d -= x * x; }
        if (j >= 3) { float x = sL3[(j - 3) * BLK + t]; d -= x * x; }
        float inv = rsqrtf(d);
        inv = inv * (1.5f - 0.5f * d * inv * inv);   // Newton refine -> ~1 ulp

        // off-diagonals of column j
        float s1v = a1, s2v = a2, s3v = a3;
        if (j >= 1) {
            float L1p = sL1[(j - 1) * BLK + t];
            float L2p = sL2[(j - 1) * BLK + t];
            float L3p = sL3[(j - 1) * BLK + t];
            s1v -= L2p * L1p;
            s2v -= L3p * L1p;
        }
        if (j >= 2) {
            float L2q = sL2[(j - 2) * BLK + t];
            float L3q = sL3[(j - 2) * BLK + t];
            s1v -= L3q * L2q;
        }
        if (j > NN - 2) s1v = 0.f;   // rows beyond matrix
        if (j > NN - 3) s2v = 0.f;
        if (j > NN - 4) s3v = 0.f;

        sL1[j * BLK + t] = s1v * inv;
        sL2[j * BLK + t] = s2v * inv;
        sL3[j * BLK + t] = s3v * inv;
        sinv[j * BLK + t] = inv;

        // fused forward solve: z[j] = (rhs - sum L[j][j-u] z[j-u]) * inv
        float zacc = rhs;
        if (j >= 1) zacc -= sL1[(j - 1) * BLK + t] * sz[(j - 1) * BLK + t];
        if (j >= 2) zacc -= sL2[(j - 2) * BLK + t] * sz[(j - 2) * BLK + t];
        if (j >= 3) zacc -= sL3[(j - 3) * BLK + t] * sz[(j - 3) * BLK + t];
        sz[j * BLK + t] = zacc * inv;

        cA = cB; sA = sB;
    }

    // ---- back substitution (in place), stage output into sth ----
    sth[t] = v0v;   // output column 0 = v0
    #pragma unroll 4
    for (int j = NN - 1; j >= 0; --j) {
        float acc = sz[j * BLK + t];
        if (j <= NN - 2) acc -= sL1[j * BLK + t] * sz[(j + 1) * BLK + t];
        if (j <= NN - 3) acc -= sL2[j * BLK + t] * sz[(j + 2) * BLK + t];
        if (j <= NN - 4) acc -= sL3[j * BLK + t] * sz[(j + 3) * BLK + t];
        float y = acc * sinv[j * BLK + t];
        sz[j * BLK + t] = y;
        sth[(j + 1) * BLK + t] = y;
    }
    __syncthreads();

    // ---- coalesced store ----
    for (int idx = t; idx < BLK * NP; idx += BLK) {
        int bl = idx / NP;
        int k  = idx - bl * NP;
        out[(size_t)b0 * NP + idx] = sth[k * BLK + bl];
    }
}

extern "C" void kernel_launch(void* const* d_in, const int* in_sizes, int n_in,
                              void* d_out, int out_size) {
    const float* dxy   = (const float*)d_in[0];
    const float* theta = (const float*)d_in[1];
    const float* v0    = (const float*)d_in[2];
    float* out = (float*)d_out;
    int B = in_sizes[2];

    size_t smem = (size_t)SMEM_FLOATS * sizeof(float);
    cudaFuncSetAttribute(AlpamayoR1_solve_kernel,
                         cudaFuncAttributeMaxDynamicSharedMemorySize, (int)smem);
    int grid = (B + BLK - 1) / BLK;
    AlpamayoR1_solve_kernel<<<grid, BLK, smem>>>(dxy, theta, v0, out, B);
}

// round 2
// speedup vs baseline: 1.8655x; 1.8655x over previous
#include <cuda_runtime.h>

#define BLK  64     // batches per CTA == threads per CTA
#define BLKP 65     // padded shared row stride (bank-conflict-free)
#define NN   64     // number of unknowns (N)
#define NP   65     // N + 1
#define LAM3  1e-4f // V_LAMBDA / DT^6 (DT = 1)
#define RIDGE 1e-4f

// Shared layout (floats, all rows stride BLKP):
//  sc  : NP rows   theta -> cos (later reused as output staging)
//  ss  : NP rows   sin
//  sgx : NN rows   2*dxy.x
//  sgy : NN rows   2*dxy.y
//  sL1 : NN rows   L[j+1][j]
//  sL2 : NN rows   L[j+2][j]
//  sL3 : NN rows   L[j+3][j]
//  sinvd: NN rows  1/L[j][j]
//  sz  : NN rows   forward-solve result
//  sCb : 4*NP      constant DTD band coefficients
#define SMEM_FLOATS ((2*NP + 7*NN)*BLKP + 4*NP)

__global__ __launch_bounds__(BLK) void AlpamayoR1_solve_kernel(
    const float* __restrict__ dxy,
    const float* __restrict__ theta,
    const float* __restrict__ v0,
    float* __restrict__ out, int B)
{
    extern __shared__ float sm[];
    float* sc   = sm;
    float* ss   = sc   + NP*BLKP;
    float* sgx  = ss   + NP*BLKP;
    float* sgy  = sgx  + NN*BLKP;
    float* sL1  = sgy  + NN*BLKP;
    float* sL2  = sL1  + NN*BLKP;
    float* sL3  = sL2  + NN*BLKP;
    float* sivd = sL3  + NN*BLKP;
    float* sz   = sivd + NN*BLKP;
    float* sCb  = sz   + NN*BLKP;

    const int t  = threadIdx.x;
    const int b0 = blockIdx.x * BLK;

    // ---- constant DTD band: C(a,m) = lam3 * sum_r D3[r,a]*D3[r,a+m] ----
    for (int a = t; a < NP; a += BLK) {
        const float coef[4] = {-1.f, 3.f, -3.f, 1.f};
        const int Mrows = NP - 3;  // 62
        #pragma unroll
        for (int m = 0; m < 4; m++) {
            float acc = 0.f;
            int tmin = a - (Mrows - 1); if (tmin < 0) tmin = 0;
            int tmax = 3 - m;           if (tmax > a) tmax = a;
            for (int tt = tmin; tt <= tmax; tt++) acc += coef[tt] * coef[tt + m];
            sCb[m * NP + a] = LAM3 * acc;
        }
    }

    // ---- coalesced load + transpose into padded shared ----
    for (int idx = t; idx < BLK * NP; idx += BLK) {
        int bl = idx / NP;
        int k  = idx - bl * NP;
        sc[k * BLKP + bl] = theta[(size_t)b0 * NP + idx];
    }
    const float2* dxy2 = (const float2*)dxy;
    for (int idx = t; idx < BLK * NN; idx += BLK) {
        float2 v = dxy2[(size_t)b0 * NN + idx];
        int bl = idx / NN;
        int i  = idx - bl * NN;
        sgx[i * BLKP + bl] = 2.0f * v.x;
        sgy[i * BLKP + bl] = 2.0f * v.y;
    }
    float v0v = v0[b0 + t];
    __syncthreads();

    // ---- sincos pre-pass (in place; each thread owns its column) ----
    #pragma unroll
    for (int k = 0; k < NP; k++) {
        float th = sc[k * BLKP + t];
        float s, c;
        __sincosf(th, &s, &c);
        sc[k * BLKP + t] = c;
        ss[k * BLKP + t] = s;
    }

    // ---- band assembly + band Cholesky + fused forward solve ----
    float c0 = sc[t],            s0 = ss[t];
    float cA = sc[BLKP + t],     sA = ss[BLKP + t];
    const float e0 = c0 * cA + s0 * sA;

    float L1p = 0.f;
    float L2p1 = 0.f, L2p2 = 0.f;
    float L3p1 = 0.f, L3p2 = 0.f, L3p3 = 0.f;
    float zp1 = 0.f, zp2 = 0.f, zp3 = 0.f;

    #pragma unroll 8
    for (int j = 0; j < NN; ++j) {
        float cB = 0.f, sB = 0.f, gx1 = 0.f, gy1 = 0.f;
        if (j < NN - 1) {
            cB  = sc[(j + 2) * BLKP + t];
            sB  = ss[(j + 2) * BLKP + t];
            gx1 = sgx[(j + 1) * BLKP + t];
            gy1 = sgy[(j + 1) * BLKP + t];
        }
        float e1 = cA * cB + sA * sB;

        float gxj = sgx[j * BLKP + t];
        float gyj = sgy[j * BLKP + t];
        float rhs = cA * (gxj + gx1) + sA * (gyj + gy1);
        if (j == 0) rhs -= (e0 - 3.f * LAM3) * v0v;
        if (j == 1) rhs -= (3.f * LAM3) * v0v;
        if (j == 2) rhs += LAM3 * v0v;

        float a0 = ((j < NN - 1) ? 2.f : 1.f) + sCb[0 * NP + (j + 1)] + RIDGE;
        float a1 = e1 + sCb[1 * NP + (j + 1)];
        float a2 = sCb[2 * NP + (j + 1)];
        float a3 = sCb[3 * NP + (j + 1)];

        // pivot (critical chain: all operands in registers)
        float d = a0 - L1p * L1p - L2p2 * L2p2 - L3p3 * L3p3;
        float inv = rsqrtf(d);

        float s1v = a1 - L2p1 * L1p - L3p2 * L2p2;
        float s2v = a2 - L3p1 * L1p;
        float s3v = a3;
        if (j > NN - 2) s1v = 0.f;
        if (j > NN - 3) s2v = 0.f;
        if (j > NN - 4) s3v = 0.f;

        float L1 = s1v * inv;
        float L2 = s2v * inv;
        float L3 = s3v * inv;
        float z  = (rhs - L1p * zp1 - L2p2 * zp2 - L3p3 * zp3) * inv;

        sL1[j * BLKP + t]  = L1;
        sL2[j * BLKP + t]  = L2;
        sL3[j * BLKP + t]  = L3;
        sivd[j * BLKP + t] = inv;
        sz[j * BLKP + t]   = z;

        L3p3 = L3p2; L3p2 = L3p1; L3p1 = L3;
        L2p2 = L2p1; L2p1 = L2;
        L1p  = L1;
        zp3  = zp2;  zp2  = zp1;  zp1  = z;
        cA = cB; sA = sB;
    }

    // ---- back substitution (registers rolling), stage output into sc ----
    float y1 = 0.f, y2 = 0.f, y3 = 0.f;
    #pragma unroll 8
    for (int j = NN - 1; j >= 0; --j) {
        float acc = sz[j * BLKP + t]
                  - sL1[j * BLKP + t] * y1
                  - sL2[j * BLKP + t] * y2
                  - sL3[j * BLKP + t] * y3;
        float y = acc * sivd[j * BLKP + t];
        sc[(j + 1) * BLKP + t] = y;
        y3 = y2; y2 = y1; y1 = y;
    }
    sc[t] = v0v;
    __syncthreads();

    // ---- coalesced store ----
    for (int idx = t; idx < BLK * NP; idx += BLK) {
        int bl = idx / NP;
        int k  = idx - bl * NP;
        out[(size_t)b0 * NP + idx] = sc[k * BLKP + bl];
    }
}

extern "C" void kernel_launch(void* const* d_in, const int* in_sizes, int n_in,
                              void* d_out, int out_size) {
    const float* dxy   = (const float*)d_in[0];
    const float* theta = (const float*)d_in[1];
    const float* v0    = (const float*)d_in[2];
    float* out = (float*)d_out;
    int B = in_sizes[2];

    size_t smem = (size_t)SMEM_FLOATS * sizeof(float);
    cudaFuncSetAttribute(AlpamayoR1_solve_kernel,
                         cudaFuncAttributeMaxDynamicSharedMemorySize, (int)smem);
    int grid = (B + BLK - 1) / BLK;
    AlpamayoR1_solve_kernel<<<grid, BLK, smem>>>(dxy, theta, v0, out, B);
}

// round 3
// speedup vs baseline: 1.8691x; 1.0019x over previous
#include <cuda_runtime.h>

#define BLK  64     // batches per CTA == threads per CTA
#define STR  65     // padded shared row stride (bank-conflict-free)
#define NN   64     // number of unknowns (N)
#define NP   65     // N + 1
#define LAM3  1e-4f // V_LAMBDA / DT^6 (DT = 1)
#define RIDGE 1e-4f

// DTD band coefficients (times LAM3), a = column index in [1, 64]:
__device__ __forceinline__ constexpr float C0f(int a) {
    return (a == 1) ? 10.f : (a == 2) ? 19.f :
           (a <= 61) ? 20.f : (a == 62) ? 19.f : (a == 63) ? 10.f : 1.f;
}
__device__ __forceinline__ constexpr float C1f(int a) {
    return (a == 1) ? -12.f : (a <= 61) ? -15.f :
           (a == 62) ? -12.f : (a == 63) ? -3.f : 0.f;
}
__device__ __forceinline__ constexpr float C2f(int a) {
    return (a <= 61) ? 6.f : (a == 62) ? 3.f : 0.f;
}
__device__ __forceinline__ constexpr float C3f(int a) {
    return (a <= 61) ? -1.f : 0.f;
}

// Shared layout (floats, rows of stride STR):
//  sth : NP rows  theta staging
//  sgx : NN rows  2*dxy.x
//  sgy : NN rows  2*dxy.y
//  sm1/sm2/sm3 : NN rows  L[j+m][j] * inv_j   (for back-substitution)
//  szs : NN rows  z_j * inv_j
//  sou : NP rows  output staging
#define SMEM_FLOATS ((2*NP + 6*NN) * STR)

__global__ __launch_bounds__(BLK) void AlpamayoR1_solve_kernel(
    const float* __restrict__ dxy,
    const float* __restrict__ theta,
    const float* __restrict__ v0,
    float* __restrict__ out, int B)
{
    extern __shared__ float sm[];
    float* sth = sm;
    float* sgx = sth + NP*STR;
    float* sgy = sgx + NN*STR;
    float* sm1 = sgy + NN*STR;
    float* sm2 = sm1 + NN*STR;
    float* sm3 = sm2 + NN*STR;
    float* szs = sm3 + NN*STR;
    float* sou = szs + NN*STR;

    const int t  = threadIdx.x;
    const int b0 = blockIdx.x * BLK;

    // ---- coalesced load + transpose into padded shared ----
    for (int idx = t; idx < BLK * NP; idx += BLK) {
        int bl = idx / NP;
        int k  = idx - bl * NP;
        sth[k * STR + bl] = theta[(size_t)b0 * NP + idx];
    }
    const float2* dxy2 = (const float2*)dxy;
    for (int idx = t; idx < BLK * NN; idx += BLK) {
        float2 v = dxy2[(size_t)b0 * NN + idx];
        int bl = idx / NN;
        int i  = idx - bl * NN;
        sgx[i * STR + bl] = 2.0f * v.x;
        sgy[i * STR + bl] = 2.0f * v.y;
    }
    float v0v = v0[b0 + t];
    __syncthreads();

    // ---- prologue: theta_0, theta_1 ----
    float th0 = sth[t];
    float s0, c0; __sincosf(th0, &s0, &c0);
    float th1 = sth[STR + t];
    float sA, cA; __sincosf(th1, &sA, &cA);
    const float e0 = c0 * cA + s0 * sA;
    float gxj = sgx[t], gyj = sgy[t];

    // rolling Cholesky state (3-wide band)
    float L1p  = 0.f;
    float L2p1 = 0.f, L2p2 = 0.f;
    float L3p1 = 0.f, L3p2 = 0.f, L3p3 = 0.f;
    float zp1  = 0.f, zp2  = 0.f, zp3  = 0.f;

    #pragma unroll
    for (int j = 0; j < NN; ++j) {
        float cB = 0.f, sB = 0.f, gx1 = 0.f, gy1 = 0.f;
        if (j < NN - 1) {
            float th2 = sth[(j + 2) * STR + t];
            __sincosf(th2, &sB, &cB);
            gx1 = sgx[(j + 1) * STR + t];
            gy1 = sgy[(j + 1) * STR + t];
        }
        float e1  = cA * cB + sA * sB;
        float rhs = cA * (gxj + gx1) + sA * (gyj + gy1);
        if (j == 0) rhs -= (e0 - 3.f * LAM3) * v0v;
        if (j == 1) rhs -= 3.f * LAM3 * v0v;
        if (j == 2) rhs += LAM3 * v0v;

        // band of lhs, column j (compile-time constants after full unroll)
        float a0 = ((j < NN - 1) ? 2.f : 1.f) + LAM3 * C0f(j + 1) + RIDGE;
        float a1 = e1 + LAM3 * C1f(j + 1);
        float a2 = LAM3 * C2f(j + 1);
        float a3 = LAM3 * C3f(j + 1);

        // pivot (critical chain: registers only)
        float d   = a0 - L1p * L1p - L2p2 * L2p2 - L3p3 * L3p3;
        float inv = rsqrtf(d);

        float s1v = (j < NN - 1) ? (a1 - L2p1 * L1p - L3p2 * L2p2) : 0.f;
        float s2v = (j < NN - 2) ? (a2 - L3p1 * L1p) : 0.f;
        float s3v = (j < NN - 3) ? a3 : 0.f;

        float L1 = s1v * inv;
        float L2 = s2v * inv;
        float L3 = s3v * inv;
        float z  = (rhs - L1p * zp1 - L2p2 * zp2 - L3p3 * zp3) * inv;

        // pre-scaled values for back-substitution
        sm1[j * STR + t] = L1 * inv;
        sm2[j * STR + t] = L2 * inv;
        sm3[j * STR + t] = L3 * inv;
        szs[j * STR + t] = z  * inv;

        L3p3 = L3p2; L3p2 = L3p1; L3p1 = L3;
        L2p2 = L2p1; L2p1 = L2;
        L1p  = L1;
        zp3  = zp2;  zp2  = zp1;  zp1  = z;
        cA = cB; sA = sB; gxj = gx1; gyj = gy1;
    }

    // ---- back substitution: y_j = zs_j - m1_j*y1 - m2_j*y2 - m3_j*y3 ----
    float y1 = 0.f, y2 = 0.f, y3 = 0.f;
    #pragma unroll
    for (int j = NN - 1; j >= 0; --j) {
        float y = szs[j * STR + t]
                - sm1[j * STR + t] * y1
                - sm2[j * STR + t] * y2
                - sm3[j * STR + t] * y3;
        sou[(j + 1) * STR + t] = y;
        y3 = y2; y2 = y1; y1 = y;
    }
    sou[t] = v0v;
    __syncthreads();

    // ---- coalesced store ----
    for (int idx = t; idx < BLK * NP; idx += BLK) {
        int bl = idx / NP;
        int k  = idx - bl * NP;
        out[(size_t)b0 * NP + idx] = sou[k * STR + bl];
    }
}

extern "C" void kernel_launch(void* const* d_in, const int* in_sizes, int n_in,
                              void* d_out, int out_size) {
    const float* dxy   = (const float*)d_in[0];
    const float* theta = (const float*)d_in[1];
    const float* v0    = (const float*)d_in[2];
    float* out = (float*)d_out;
    int B = in_sizes[2];

    size_t smem = (size_t)SMEM_FLOATS * sizeof(float);
    cudaFuncSetAttribute(AlpamayoR1_solve_kernel,
                         cudaFuncAttributeMaxDynamicSharedMemorySize, (int)smem);
    int grid = (B + BLK - 1) / BLK;
    AlpamayoR1_solve_kernel<<<grid, BLK, smem>>>(dxy, theta, v0, out, B);
}